// round 4
// baseline (speedup 1.0000x reference)
#include <cuda_runtime.h>
#include <math.h>

#define NPKG  20000
#define NTGTN 30000
#define NE    100000
#define NTY   6
#define FIN   400
#define FD    256
#define KC    128

#define OFF_L     0LL
#define OFF_R     5120000LL
#define OFF_HPKG  12800000LL
#define OFF_HTGT  17920000LL
#define OFF_SPKG  25600000LL
#define OFF_STGT  28160000LL
#define OFF_POOL  32000000LL
#define OFF_MPKG  32229376LL
#define OFF_MT    32245760LL
#define OFF_APOOL 32262144LL
#define OFF_L2    32360448LL
#define OFF_R2    32557056LL
#define OFF_ESC   32753664LL
#define OFF_EMAX  33153664LL
#define OFF_EDEN  33273664LL
#define OFF_SCAL  33393664LL
#define SCRATCH_TOTAL 33393680LL

__device__ __align__(256) float g_scratch[SCRATCH_TOTAL];

__device__ __forceinline__ void atomicMaxFloat(float* addr, float val) {
    int old = __float_as_int(*addr);
    while (__int_as_float(old) < val) {
        int prev = atomicCAS((int*)addr, old, __float_as_int(val));
        if (prev == old) break;
        old = prev;
    }
}

__global__ void fill_kernel(float* __restrict__ p, float v, int n) {
    for (int i = blockIdx.x * blockDim.x + threadIdx.x; i < n; i += gridDim.x * blockDim.x)
        p[i] = v;
}

__global__ void relu_kernel(float* __restrict__ p, int n) {
    for (int i = blockIdx.x * blockDim.x + threadIdx.x; i < n; i += gridDim.x * blockDim.x)
        p[i] = fmaxf(p[i], 0.f);
}

// C[M,N] = A[M,K]@B[K,N] row-major; 64x64 tile, BK=16, 256 thr, 4x4/thr; batched by grid.z
__global__ __launch_bounds__(256) void sgemm_kernel(
    const float* __restrict__ A, const float* __restrict__ B, float* __restrict__ C,
    int M, int N, int Kd, int do_relu, long long sA, long long sB, long long sC)
{
    A += (long long)blockIdx.z * sA; B += (long long)blockIdx.z * sB;
    C += (long long)blockIdx.z * sC;
    __shared__ float As[16][68], Bs[16][68];
    const int tid = threadIdx.x, tx = tid & 15, ty = tid >> 4;
    const int bm = blockIdx.y << 6, bn = blockIdx.x << 6;
    const int arow = tid >> 2, acol = (tid & 3) << 2;
    const int brow = tid >> 4, bcol = (tid & 15) << 2;
    float acc[4][4];
#pragma unroll
    for (int i = 0; i < 4; i++)
#pragma unroll
        for (int j = 0; j < 4; j++) acc[i][j] = 0.f;
    const int gr = bm + arow;
    for (int k0 = 0; k0 < Kd; k0 += 16) {
        float4 av = make_float4(0.f, 0.f, 0.f, 0.f);
        if (gr < M) av = *(const float4*)(A + (long long)gr * Kd + k0 + acol);
        As[acol][arow] = av.x; As[acol + 1][arow] = av.y;
        As[acol + 2][arow] = av.z; As[acol + 3][arow] = av.w;
        *(float4*)&Bs[brow][bcol] = *(const float4*)(B + (long long)(k0 + brow) * N + bn + bcol);
        __syncthreads();
#pragma unroll
        for (int k = 0; k < 16; k++) {
            float4 a4 = *(const float4*)&As[k][ty << 2];
            float4 b4 = *(const float4*)&Bs[k][tx << 2];
            float ar[4] = {a4.x, a4.y, a4.z, a4.w};
            float br_[4] = {b4.x, b4.y, b4.z, b4.w};
#pragma unroll
            for (int i = 0; i < 4; i++)
#pragma unroll
                for (int j = 0; j < 4; j++) acc[i][j] = fmaf(ar[i], br_[j], acc[i][j]);
        }
        __syncthreads();
    }
#pragma unroll
    for (int i = 0; i < 4; i++) {
        int r = bm + (ty << 2) + i;
        if (r >= M) continue;
        float4 o = make_float4(acc[i][0], acc[i][1], acc[i][2], acc[i][3]);
        if (do_relu) { o.x = fmaxf(o.x, 0.f); o.y = fmaxf(o.y, 0.f);
                       o.z = fmaxf(o.z, 0.f); o.w = fmaxf(o.w, 0.f); }
        *(float4*)(C + (long long)r * N + bn + (tx << 2)) = o;
    }
}

// C[K1,K2] += A[N,K1]^T @ B[N,K2], atomic accumulate, N split by grid.z
__global__ __launch_bounds__(256) void atb_kernel(
    const float* __restrict__ A, const float* __restrict__ B, float* __restrict__ C,
    int N, int K1, int K2)
{
    __shared__ float As[16][68], Bs[16][68];
    const int tid = threadIdx.x, tx = tid & 15, ty = tid >> 4;
    const int bk1 = blockIdx.y << 6, bk2 = blockIdx.x << 6;
    int chunk = ((N + gridDim.z - 1) / gridDim.z + 15) & ~15;
    int n0 = blockIdx.z * chunk, n1 = min(n0 + chunk, N);
    const int lrow = tid >> 4, lcol = (tid & 15) << 2;
    float acc[4][4];
#pragma unroll
    for (int i = 0; i < 4; i++)
#pragma unroll
        for (int j = 0; j < 4; j++) acc[i][j] = 0.f;
    for (int nb = n0; nb < n1; nb += 16) {
        int gn = nb + lrow;
        float4 a = make_float4(0.f, 0.f, 0.f, 0.f), b = a;
        if (gn < N) {
            a = *(const float4*)(A + (long long)gn * K1 + bk1 + lcol);
            b = *(const float4*)(B + (long long)gn * K2 + bk2 + lcol);
        }
        *(float4*)&As[lrow][lcol] = a;
        *(float4*)&Bs[lrow][lcol] = b;
        __syncthreads();
#pragma unroll
        for (int k = 0; k < 16; k++) {
            float4 a4 = *(const float4*)&As[k][ty << 2];
            float4 b4 = *(const float4*)&Bs[k][tx << 2];
            float ar[4] = {a4.x, a4.y, a4.z, a4.w};
            float br_[4] = {b4.x, b4.y, b4.z, b4.w};
#pragma unroll
            for (int i = 0; i < 4; i++)
#pragma unroll
                for (int j = 0; j < 4; j++) acc[i][j] = fmaf(ar[i], br_[j], acc[i][j]);
        }
        __syncthreads();
    }
#pragma unroll
    for (int i = 0; i < 4; i++) {
        int r = bk1 + (ty << 2) + i;
#pragma unroll
        for (int j = 0; j < 4; j++)
            atomicAdd(&C[(long long)r * K2 + bk2 + (tx << 2) + j], acc[i][j]);
    }
}

// rows of width 128: softmax in-place + entropy accumulation (warp per row)
__global__ void softmax_ent_kernel(float* __restrict__ S, int N, float inv_n,
                                   float* __restrict__ ent_acc)
{
    int g = blockIdx.x * blockDim.x + threadIdx.x;
    int w = g >> 5, lane = g & 31;
    if (w >= N) return;
    float* row = S + (long long)w * KC;
    float v0 = row[lane], v1 = row[lane + 32], v2 = row[lane + 64], v3 = row[lane + 96];
    float m = fmaxf(fmaxf(v0, v1), fmaxf(v2, v3));
    for (int o = 16; o; o >>= 1) m = fmaxf(m, __shfl_xor_sync(~0u, m, o));
    v0 = expf(v0 - m); v1 = expf(v1 - m); v2 = expf(v2 - m); v3 = expf(v3 - m);
    float s = v0 + v1 + v2 + v3;
    for (int o = 16; o; o >>= 1) s += __shfl_xor_sync(~0u, s, o);
    float inv = 1.f / s;
    v0 *= inv; v1 *= inv; v2 *= inv; v3 *= inv;
    row[lane] = v0; row[lane + 32] = v1; row[lane + 64] = v2; row[lane + 96] = v3;
    float e = -(v0 * logf(v0 + 1e-15f) + v1 * logf(v1 + 1e-15f)
              + v2 * logf(v2 + 1e-15f) + v3 * logf(v3 + 1e-15f));
    for (int o = 16; o; o >>= 1) e += __shfl_xor_sync(~0u, e, o);
    if (lane == 0) atomicAdd(ent_acc, e * inv_n);
}

__global__ __launch_bounds__(256) void edge_score_kernel(
    const float* __restrict__ l, const float* __restrict__ r,
    const int* __restrict__ src, const int* __restrict__ tgt,
    const float* __restrict__ a1, float* __restrict__ esc, float* __restrict__ emax)
{
    __shared__ float a_s[256];
    int tid = threadIdx.x;
    a_s[tid] = a1[tid];
    __syncthreads();
    int g = blockIdx.x * blockDim.x + tid;
    int e = g >> 5, lane = g & 31;
    if (e >= NE) return;
    int t = tgt[e];
    const float* lr = l + (long long)src[e] * FD;
    const float* rr = r + (long long)t * FD;
#pragma unroll
    for (int h = 0; h < 4; h++) {
        float acc = 0.f;
#pragma unroll
        for (int q = 0; q < 2; q++) {
            int c = h * 64 + lane + q * 32;
            float v = lr[c] + rr[c];
            v = v > 0.f ? v : 0.2f * v;
            acc = fmaf(v, a_s[c], acc);
        }
        for (int o = 16; o; o >>= 1) acc += __shfl_xor_sync(~0u, acc, o);
        if (lane == 0) { esc[e * 4 + h] = acc; atomicMaxFloat(&emax[t * 4 + h], acc); }
    }
}

__global__ void edge_exp_kernel(const int* __restrict__ tgt, float* __restrict__ esc,
                                const float* __restrict__ emax, float* __restrict__ eden)
{
    int idx = blockIdx.x * blockDim.x + threadIdx.x;
    if (idx >= NE * 4) return;
    int e = idx >> 2, h = idx & 3;
    int t = tgt[e];
    float m = emax[t * 4 + h];
    if (!isfinite(m)) m = 0.f;
    float ex = expf(esc[idx] - m);
    esc[idx] = ex;
    atomicAdd(&eden[t * 4 + h], ex);
}

__global__ __launch_bounds__(256) void edge_aggr_kernel(
    const float* __restrict__ l, const int* __restrict__ src, const int* __restrict__ tgt,
    const float* __restrict__ esc, const float* __restrict__ eden, float* __restrict__ outh)
{
    int g = blockIdx.x * blockDim.x + threadIdx.x;
    int e = g >> 5, lane = g & 31;
    if (e >= NE) return;
    int s = src[e], t = tgt[e];
    float alpha[4];
#pragma unroll
    for (int h = 0; h < 4; h++)
        alpha[h] = esc[e * 4 + h] / (eden[t * 4 + h] + 1e-16f);
    const float* lr = l + (long long)s * FD;
    float* orow = outh + (long long)t * FD;
#pragma unroll
    for (int q = 0; q < 8; q++) {
        int c = lane + q * 32;
        atomicAdd(&orow[c], lr[c] * alpha[c >> 6]);
    }
}

// A_pool[t] += sum_e outer(S_pkg[src[e]], S_tgt[tgt[e]])
__global__ __launch_bounds__(256) void apool_kernel(
    const float* __restrict__ Spkg, const float* __restrict__ Stgt,
    const int* __restrict__ src, const int* __restrict__ tgt, float* __restrict__ Apool)
{
    __shared__ float ss[128], st[128];
    int tid = threadIdx.x, k = tid & 127, half = tid >> 7;
    float acc[64];
#pragma unroll
    for (int j = 0; j < 64; j++) acc[j] = 0.f;
    int per = (NE + gridDim.x - 1) / gridDim.x;
    int e0 = blockIdx.x * per, e1 = min(e0 + per, NE);
    for (int e = e0; e < e1; e++) {
        __syncthreads();
        if (half == 0) ss[k] = Spkg[(long long)src[e] * KC + k];
        else           st[k] = Stgt[(long long)tgt[e] * KC + k];
        __syncthreads();
        float a = ss[k];
        const float* p = &st[half << 6];
#pragma unroll
        for (int j = 0; j < 64; j++) acc[j] = fmaf(a, p[j], acc[j]);
    }
    float* dst = Apool + k * KC + (half << 6);
#pragma unroll
    for (int j = 0; j < 64; j++) atomicAdd(&dst[j], acc[j]);
}

__global__ void mulsum_kernel(const float* __restrict__ a, const float* __restrict__ b,
                              int n, float* __restrict__ slot)
{
    __shared__ float sred[8];
    float acc = 0.f;
    for (int i = blockIdx.x * blockDim.x + threadIdx.x; i < n; i += gridDim.x * blockDim.x)
        acc += a[i] * b[i];
    for (int o = 16; o; o >>= 1) acc += __shfl_xor_sync(~0u, acc, o);
    if ((threadIdx.x & 31) == 0) sred[threadIdx.x >> 5] = acc;
    __syncthreads();
    if (threadIdx.x == 0) {
        float t = 0.f;
        for (int i = 0; i < (int)(blockDim.x >> 5); i++) t += sred[i];
        atomicAdd(slot, t);
    }
}

__global__ __launch_bounds__(256) void edge_dot_kernel(
    const float* __restrict__ Spkg, const float* __restrict__ Stgt,
    const int* __restrict__ src, const int* __restrict__ tgt, float* __restrict__ slot)
{
    __shared__ float sred[8];
    int g = blockIdx.x * blockDim.x + threadIdx.x;
    int e = g >> 5, lane = threadIdx.x & 31;
    float acc = 0.f;
    if (e < NE) {
        const float* a = Spkg + (long long)src[e] * KC;
        const float* b = Stgt + (long long)tgt[e] * KC;
#pragma unroll
        for (int q = 0; q < 4; q++) acc += a[lane + q * 32] * b[lane + q * 32];
    }
    for (int o = 16; o; o >>= 1) acc += __shfl_xor_sync(~0u, acc, o);
    if (lane == 0) sred[threadIdx.x >> 5] = acc;
    __syncthreads();
    if (threadIdx.x == 0) {
        float t = 0.f;
        for (int i = 0; i < 8; i++) t += sred[i];
        atomicAdd(slot, t);
    }
}

__global__ void link_combine_kernel(float* __restrict__ scal) {
    float n2 = fmaxf((float)NE - 2.f * scal[2] + scal[3], 0.f) + 1e-12f;
    scal[1] += sqrtf(n2) * (1.f / ((float)NPKG * (float)NTGTN));
    scal[2] = 0.f; scal[3] = 0.f;
}

// conv2 scores: one warp per (t,i,j) pair -> e2 masked scores
__global__ __launch_bounds__(256) void attn2_score_kernel(
    const float* __restrict__ l2, const float* __restrict__ r2,
    const float* __restrict__ Apool, const float* __restrict__ a2, float* __restrict__ e2)
{
    int g = blockIdx.x * blockDim.x + threadIdx.x;
    int w = g >> 5, lane = g & 31;
    if (w >= NTY * KC * KC) return;
    int t = w >> 14, rem = w & 16383, i = rem >> 7, j = rem & 127;
    const float* li = l2 + ((long long)t * KC + i) * FD;
    const float* rj = r2 + ((long long)t * KC + j) * FD;
    const float* av = a2 + t * 256;
    float ap = Apool[(long long)t * KC * KC + i * KC + j];
#pragma unroll
    for (int h = 0; h < 4; h++) {
        float acc = 0.f;
#pragma unroll
        for (int q = 0; q < 2; q++) {
            int c = h * 64 + lane + q * 32;
            float v = li[c] + rj[c];
            v = v > 0.f ? v : 0.2f * v;
            acc = fmaf(v, av[c], acc);
        }
        for (int o = 16; o; o >>= 1) acc += __shfl_xor_sync(~0u, acc, o);
        if (lane == 0) e2[(long long)w * 4 + h] = (ap > 0.f) ? acc : -1e9f;
    }
}

// softmax over i (source clusters) for fixed (t,j,h); block=(j,t), 128 threads=i
__global__ __launch_bounds__(128) void attn2_softmax_kernel(
    const float* __restrict__ e2, float* __restrict__ out_attn)
{
    int j = blockIdx.x, t = blockIdx.y, i = threadIdx.x;
    int lane = i & 31, wid = i >> 5;
    __shared__ float wred[4][4];
    long long base = (((long long)t * KC + i) * KC + j) * 4;
    float e[4], m[4], ex[4];
#pragma unroll
    for (int h = 0; h < 4; h++) e[h] = e2[base + h];
#pragma unroll
    for (int h = 0; h < 4; h++) {
        float x = e[h];
        for (int o = 16; o; o >>= 1) x = fmaxf(x, __shfl_xor_sync(~0u, x, o));
        if (lane == 0) wred[wid][h] = x;
    }
    __syncthreads();
#pragma unroll
    for (int h = 0; h < 4; h++)
        m[h] = fmaxf(fmaxf(wred[0][h], wred[1][h]), fmaxf(wred[2][h], wred[3][h]));
    __syncthreads();
#pragma unroll
    for (int h = 0; h < 4; h++) {
        ex[h] = expf(e[h] - m[h]);
        float x = ex[h];
        for (int o = 16; o; o >>= 1) x += __shfl_xor_sync(~0u, x, o);
        if (lane == 0) wred[wid][h] = x;
    }
    __syncthreads();
#pragma unroll
    for (int h = 0; h < 4; h++) {
        float sm = wred[0][h] + wred[1][h] + wred[2][h] + wred[3][h];
        out_attn[base + h] = ex[h] / sm;
    }
}

__global__ void cls_kernel(const float* __restrict__ pool, const float* __restrict__ Wcls,
                           const float* __restrict__ bcls, float* __restrict__ out)
{
    int g = blockIdx.x * blockDim.x + threadIdx.x;
    int w = g >> 5, lane = g & 31;
    if (w >= (NTY + 1) * KC) return;
    const float* row = pool + (long long)w * FD;
    float acc = 0.f;
#pragma unroll
    for (int q = 0; q < 8; q++) acc += row[lane + q * 32] * Wcls[lane + q * 32];
    for (int o = 16; o; o >>= 1) acc += __shfl_xor_sync(~0u, acc, o);
    if (lane == 0) out[w] = 1.f / (1.f + expf(-(acc + bcls[0])));
}

__global__ void finalize_kernel(const float* __restrict__ scal, float* __restrict__ out) {
    out[(NTY + 1) * KC] = scal[0] + scal[1];
}

extern "C" void kernel_launch(void* const* d_in, const int* in_sizes, int n_in,
                              void* d_out, int out_size)
{
    (void)in_sizes; (void)n_in; (void)out_size;
    const float* x_pkg   = (const float*)d_in[0];
    const float* x_tgt   = (const float*)d_in[1];
    const int*   src_idx = (const int*)d_in[2];
    const int*   tgt_idx = (const int*)d_in[3];
    const float* W1s     = (const float*)d_in[4];
    const float* W1t     = (const float*)d_in[5];
    const float* a1      = (const float*)d_in[6];
    const float* Wpkg    = (const float*)d_in[7];
    const float* Wassign = (const float*)d_in[8];
    const float* W2s     = (const float*)d_in[9];
    const float* W2t     = (const float*)d_in[10];
    const float* a2      = (const float*)d_in[11];
    const float* Wcls    = (const float*)d_in[12];
    const float* bcls    = (const float*)d_in[13];
    float* out = (float*)d_out;

    void* sp = nullptr;
    cudaGetSymbolAddress(&sp, g_scratch);
    float* S = (float*)sp;
    float* bl    = S + OFF_L;
    float* brr   = S + OFF_R;
    float* hpkg  = S + OFF_HPKG;
    float* htgt  = S + OFF_HTGT;
    float* Spkg  = S + OFF_SPKG;
    float* Stgt  = S + OFF_STGT;
    float* pool  = S + OFF_POOL;
    float* Mpkg  = S + OFF_MPKG;
    float* Mt    = S + OFF_MT;
    float* Apool = S + OFF_APOOL;
    float* l2    = S + OFF_L2;
    float* r2    = S + OFF_R2;
    float* esc   = S + OFF_ESC;
    float* emax  = S + OFF_EMAX;
    float* eden  = S + OFF_EDEN;
    float* scal  = S + OFF_SCAL;

    fill_kernel<<<1, 32>>>(scal, 0.f, 16);
    fill_kernel<<<512, 256>>>(pool, 0.f, 7 * KC * FD);
    fill_kernel<<<64, 256>>>(Mpkg, 0.f, KC * KC);
    fill_kernel<<<256, 256>>>(Apool, 0.f, NTY * KC * KC);

    // h_pkg, S_pkg, p_pkg, M_pkg
    sgemm_kernel<<<dim3(FD / 64, (NPKG + 63) / 64), 256>>>(
        x_pkg, Wpkg, hpkg, NPKG, FD, FIN, 1, 0, 0, 0);
    sgemm_kernel<<<dim3(KC / 64, (NPKG + 63) / 64), 256>>>(
        hpkg, Wassign, Spkg, NPKG, KC, FD, 0, 0, 0, 0);
    softmax_ent_kernel<<<(NPKG + 7) / 8, 256>>>(Spkg, NPKG, 1.0f / NPKG, scal);
    atb_kernel<<<dim3(FD / 64, KC / 64, 64), 256>>>(Spkg, hpkg, pool, NPKG, KC, FD);
    atb_kernel<<<dim3(KC / 64, KC / 64, 128), 256>>>(Spkg, Spkg, Mpkg, NPKG, KC, KC);

    for (int t = 0; t < NTY; t++) {
        const float* xt = x_tgt + (long long)t * NTGTN * FIN;
        const int* se = src_idx + (long long)t * NE;
        const int* te = tgt_idx + (long long)t * NE;

        sgemm_kernel<<<dim3(FD / 64, (NPKG + 63) / 64), 256>>>(
            x_pkg, W1s + (long long)t * FIN * FD, bl, NPKG, FD, FIN, 0, 0, 0, 0);
        sgemm_kernel<<<dim3(FD / 64, (NTGTN + 63) / 64), 256>>>(
            xt, W1t + (long long)t * FIN * FD, brr, NTGTN, FD, FIN, 0, 0, 0, 0);

        fill_kernel<<<128, 256>>>(emax, -INFINITY, NTGTN * 4);
        fill_kernel<<<128, 256>>>(eden, 0.f, NTGTN * 4);
        fill_kernel<<<1024, 256>>>(htgt, 0.f, NTGTN * FD);

        edge_score_kernel<<<NE * 32 / 256, 256>>>(bl, brr, se, te, a1 + t * 256, esc, emax);
        edge_exp_kernel<<<(NE * 4 + 255) / 256, 256>>>(te, esc, emax, eden);
        edge_aggr_kernel<<<NE * 32 / 256, 256>>>(bl, se, te, esc, eden, htgt);
        relu_kernel<<<1024, 256>>>(htgt, NTGTN * FD);

        sgemm_kernel<<<dim3(KC / 64, (NTGTN + 63) / 64), 256>>>(
            htgt, Wassign + (long long)(t + 1) * FD * KC, Stgt, NTGTN, KC, FD, 0, 0, 0, 0);
        softmax_ent_kernel<<<(NTGTN + 7) / 8, 256>>>(Stgt, NTGTN, 1.0f / NTGTN, scal);

        atb_kernel<<<dim3(FD / 64, KC / 64, 64), 256>>>(
            Stgt, htgt, pool + (long long)(t + 1) * KC * FD, NTGTN, KC, FD);
        fill_kernel<<<64, 256>>>(Mt, 0.f, KC * KC);
        atb_kernel<<<dim3(KC / 64, KC / 64, 128), 256>>>(Stgt, Stgt, Mt, NTGTN, KC, KC);

        edge_dot_kernel<<<NE * 32 / 256, 256>>>(Spkg, Stgt, se, te, scal + 2);
        mulsum_kernel<<<8, 256>>>(Mpkg, Mt, KC * KC, scal + 3);
        link_combine_kernel<<<1, 1>>>(scal);

        apool_kernel<<<896, 256>>>(Spkg, Stgt, se, te, Apool + (long long)t * KC * KC);
    }

    // conv2 projections (batched over 6 types)
    sgemm_kernel<<<dim3(FD / 64, KC / 64, NTY), 256>>>(
        pool, W2s, l2, KC, FD, FD, 0, 0, (long long)FD * FD, (long long)KC * FD);
    sgemm_kernel<<<dim3(FD / 64, KC / 64, NTY), 256>>>(
        pool + (long long)KC * FD, W2t, r2, KC, FD, FD, 0,
        (long long)KC * FD, (long long)FD * FD, (long long)KC * FD);

    attn2_score_kernel<<<NTY * KC * KC * 32 / 256, 256>>>(l2, r2, Apool, a2, esc);
    attn2_softmax_kernel<<<dim3(KC, NTY), 128>>>(esc, out + (NTY + 1) * KC + 1);

    cls_kernel<<<(NTY + 1) * KC * 32 / 256, 256>>>(pool, Wcls, bcls, out);
    finalize_kernel<<<1, 1>>>(scal, out);
}